// round 1
// baseline (speedup 1.0000x reference)
#include <cuda_runtime.h>
#include <math.h>

#define NB 4096
#define ND 1024
#define KBIN 128
#define HASHN 2048
#define EMPTYV 0xFFFFFFFFu
#define LOGN 6.9314718055994530942  // log(1024)

// accumulators: 0..6 Hsum (H1,H2,H3,H13,H23,H12,H123), 7..13 sce_sum, 14..20 kl_sum, 21 mse_sum
__device__ double g_acc[24];
__device__ unsigned g_minkey[3];
__device__ float g_part[3 * NB * 6];

__device__ __forceinline__ unsigned fkey(float f) {
    unsigned u = __float_as_uint(f);
    return (u & 0x80000000u) ? ~u : (u | 0x80000000u);
}
__device__ __forceinline__ float funkey(unsigned k) {
    unsigned u = (k & 0x80000000u) ? (k ^ 0x80000000u) : ~k;
    return __uint_as_float(u);
}

__global__ void init_kernel() {
    int t = threadIdx.x;
    if (t < 24) g_acc[t] = 0.0;
    if (t < 3) g_minkey[t] = EMPTYV;
}

__global__ void __launch_bounds__(256) min_kernel(
    const float* __restrict__ d1, const float* __restrict__ d2, const float* __restrict__ d3) {
    const float* arr = (blockIdx.y == 0) ? d1 : (blockIdx.y == 1 ? d2 : d3);
    const float4* v = (const float4*)arr;
    int n4 = (NB * ND) / 4;
    unsigned m = EMPTYV;
    for (int i = blockIdx.x * blockDim.x + threadIdx.x; i < n4; i += gridDim.x * blockDim.x) {
        float4 x = v[i];
        float mn = fminf(fminf(x.x, x.y), fminf(x.z, x.w));
        m = min(m, fkey(mn));
    }
    for (int o = 16; o > 0; o >>= 1) m = min(m, __shfl_down_sync(0xffffffffu, m, o));
    __shared__ unsigned s[8];
    int w = threadIdx.x >> 5, l = threadIdx.x & 31;
    if (l == 0) s[w] = m;
    __syncthreads();
    if (threadIdx.x == 0) {
        unsigned r = s[0];
#pragma unroll
        for (int i = 1; i < 8; i++) r = min(r, s[i]);
        atomicMin(&g_minkey[blockIdx.y], r);
    }
}

__global__ void __launch_bounds__(256) mse_kernel(
    const float* __restrict__ d, const float* __restrict__ o) {
    const float4* dv = (const float4*)d;
    const float4* ov = (const float4*)o;
    int n4 = NB * 3 * ND / 4;
    float acc = 0.f;
    for (int i = blockIdx.x * blockDim.x + threadIdx.x; i < n4; i += gridDim.x * blockDim.x) {
        float4 a = dv[i], b = ov[i];
        float x0 = a.x - b.x, x1 = a.y - b.y, x2 = a.z - b.z, x3 = a.w - b.w;
        acc += x0 * x0 + x1 * x1 + x2 * x2 + x3 * x3;
    }
    for (int s = 16; s > 0; s >>= 1) acc += __shfl_down_sync(0xffffffffu, acc, s);
    __shared__ float red[8];
    int w = threadIdx.x >> 5, l = threadIdx.x & 31;
    if (l == 0) red[w] = acc;
    __syncthreads();
    if (threadIdx.x == 0) {
        float r = red[0];
#pragma unroll
        for (int i = 1; i < 8; i++) r += red[i];
        atomicAdd(&g_acc[21], (double)r);
    }
}

__device__ __forceinline__ float blockSum(float v, float* red) {
    for (int o = 16; o > 0; o >>= 1) v += __shfl_down_sync(0xffffffffu, v, o);
    int w = threadIdx.x >> 5, l = threadIdx.x & 31;
    __syncthreads();
    if (l == 0) red[w] = v;
    __syncthreads();
    float r = red[0];
#pragma unroll
    for (int i = 1; i < 8; i++) r += red[i];
    return r;
}
__device__ __forceinline__ float blockMax(float v, float* red) {
    for (int o = 16; o > 0; o >>= 1) v = fmaxf(v, __shfl_down_sync(0xffffffffu, v, o));
    int w = threadIdx.x >> 5, l = threadIdx.x & 31;
    __syncthreads();
    if (l == 0) red[w] = v;
    __syncthreads();
    float r = red[0];
#pragma unroll
    for (int i = 1; i < 8; i++) r = fmaxf(r, red[i]);
    return r;
}

__global__ void __launch_bounds__(256) row_kernel(
    const float* __restrict__ d1, const float* __restrict__ d2, const float* __restrict__ d3,
    const float* __restrict__ o1, const float* __restrict__ o2, const float* __restrict__ o3) {
    __shared__ unsigned char code[3][ND];
    __shared__ unsigned hist[3][KBIN];
    __shared__ unsigned hash[HASHN];
    __shared__ float red[8];

    int row = blockIdx.x;
    int t = threadIdx.x;
    const float* dp[3] = {d1 + (size_t)row * ND, d2 + (size_t)row * ND, d3 + (size_t)row * ND};
    const float* op[3] = {o1 + (size_t)row * ND, o2 + (size_t)row * ND, o3 + (size_t)row * ND};

    float lower[3];
#pragma unroll
    for (int k = 0; k < 3; k++) lower[k] = floorf(funkey(g_minkey[k]));

    float vd[3][4], vo[3][4];
#pragma unroll
    for (int k = 0; k < 3; k++)
#pragma unroll
        for (int j = 0; j < 4; j++) {
            vd[k][j] = dp[k][t + j * 256];
            vo[k][j] = op[k][t + j * 256];
        }

    for (int i = t; i < 3 * KBIN; i += 256) ((unsigned*)hist)[i] = 0u;
    __syncthreads();

    // bin codes + single histograms
#pragma unroll
    for (int k = 0; k < 3; k++)
#pragma unroll
        for (int j = 0; j < 4; j++) {
            float q = ceilf((vd[k][j] - lower[k]) / 0.175f) - 1.0f;
            q = fminf(fmaxf(q, 0.0f), 127.0f);
            int c = (int)q;
            code[k][t + j * 256] = (unsigned char)c;
            atomicAdd(&hist[k][c], 1u);
        }

    // softmax partials per part (block reductions include syncthreads)
#pragma unroll
    for (int k = 0; k < 3; k++) {
        float m = fmaxf(fmaxf(vd[k][0], vd[k][1]), fmaxf(vd[k][2], vd[k][3]));
        m = blockMax(m, red);
        float s = 0.f, ao = 0.f, ad = 0.f;
#pragma unroll
        for (int j = 0; j < 4; j++) {
            float e = expf(vd[k][j] - m);
            s += e;
            ao += e * vo[k][j];
            ad += e * vd[k][j];
        }
        s = blockSum(s, red);
        ao = blockSum(ao, red);
        ad = blockSum(ad, red);
        float mo = fmaxf(fmaxf(vo[k][0], vo[k][1]), fmaxf(vo[k][2], vo[k][3]));
        mo = blockMax(mo, red);
        float so = 0.f;
#pragma unroll
        for (int j = 0; j < 4; j++) so += expf(vo[k][j] - mo);
        so = blockSum(so, red);
        if (t == 0) {
            float* p = &g_part[((size_t)k * NB + row) * 6];
            p[0] = m; p[1] = s; p[2] = ao; p[3] = ad; p[4] = mo; p[5] = so;
        }
    }
    __syncthreads();

    // single-code entropies: H = log(n) - (1/n) * sum_v c*log(c)
#pragma unroll
    for (int k = 0; k < 3; k++) {
        float a = 0.f;
        for (int i = t; i < KBIN; i += 256) {
            unsigned c = hist[k][i];
            if (c > 1u) a += (float)c * logf((float)c);
        }
        a = blockSum(a, red);
        if (t == 0) atomicAdd(&g_acc[k], LOGN - (double)a / 1024.0);
    }

    // composite codes: (i1,i3)->3, (i2,i3)->4, (i1,i2)->5, triple->6
    const int pa[3] = {0, 1, 0};
    const int pb[3] = {2, 2, 1};
    for (int cidx = 0; cidx < 4; cidx++) {
        __syncthreads();
        for (int i = t; i < HASHN; i += 256) hash[i] = EMPTYV;
        __syncthreads();
        for (int i = t; i < ND; i += 256) {
            unsigned key;
            if (cidx < 3)
                key = (unsigned)code[pa[cidx]][i] * 128u + (unsigned)code[pb[cidx]][i];
            else
                key = ((unsigned)code[0][i] * 128u + (unsigned)code[1][i]) * 128u +
                      (unsigned)code[2][i];
            unsigned h = (key * 2654435761u) >> 21;
            for (;;) {
                unsigned v = hash[h];
                if (v == EMPTYV) {
                    unsigned old = atomicCAS(&hash[h], EMPTYV, (key << 11) | 1u);
                    if (old == EMPTYV) break;
                    v = old;
                }
                if ((v >> 11) == key) {
                    atomicAdd(&hash[h], 1u);
                    break;
                }
                h = (h + 1) & (HASHN - 1);
            }
        }
        __syncthreads();
        float a = 0.f;
        for (int i = t; i < HASHN; i += 256) {
            unsigned v = hash[i];
            if (v != EMPTYV) {
                unsigned c = v & 0x7FFu;
                if (c > 1u) a += (float)c * logf((float)c);
            }
        }
        a = blockSum(a, red);
        if (t == 0) atomicAdd(&g_acc[3 + cidx], LOGN - (double)a / 1024.0);
    }
}

__global__ void __launch_bounds__(256) combine_kernel() {
    int row = blockIdx.x * blockDim.x + threadIdx.x;
    double sce[7], kl[7];
#pragma unroll
    for (int s = 0; s < 7; s++) { sce[s] = 0.0; kl[s] = 0.0; }
    if (row < NB) {
        double Md[3], Sd[3], Ao[3], Ad[3], Mo[3], So[3];
#pragma unroll
        for (int k = 0; k < 3; k++) {
            const float* p = &g_part[((size_t)k * NB + row) * 6];
            Md[k] = p[0]; Sd[k] = p[1]; Ao[k] = p[2]; Ad[k] = p[3]; Mo[k] = p[4]; So[k] = p[5];
        }
        // sets: {count, members}: 0:(1) 1:(2) 2:(3) 3:(1,3) 4:(2,3) 5:(1,2) 6:(1,2,3)
        const int sets[7][4] = {{1, 0, 0, 0}, {1, 1, 0, 0}, {1, 2, 0, 0}, {2, 0, 2, 0},
                                {2, 1, 2, 0}, {2, 0, 1, 0}, {3, 0, 1, 2}};
#pragma unroll
        for (int s = 0; s < 7; s++) {
            int n = sets[s][0];
            double mS = -1e300, moS = -1e300;
            for (int i = 0; i < n; i++) {
                int k = sets[s][1 + i];
                mS = fmax(mS, Md[k]);
                moS = fmax(moS, Mo[k]);
            }
            double Ssum = 0, AoS = 0, AdS = 0, SoS = 0;
            for (int i = 0; i < n; i++) {
                int k = sets[s][1 + i];
                double ed = exp(Md[k] - mS);
                Ssum += Sd[k] * ed;
                AoS += Ao[k] * ed;
                AdS += Ad[k] * ed;
                SoS += So[k] * exp(Mo[k] - moS);
            }
            double to = AoS / Ssum, td = AdS / Ssum;
            double LSEd = mS + log(Ssum), LSEo = moS + log(SoS);
            sce[s] = -(to - LSEo);
            kl[s] = (td - LSEd) - (to - LSEo);
        }
    }
#pragma unroll
    for (int s = 0; s < 7; s++) {
        double a = sce[s], b = kl[s];
        for (int o = 16; o > 0; o >>= 1) {
            a += __shfl_down_sync(0xffffffffu, a, o);
            b += __shfl_down_sync(0xffffffffu, b, o);
        }
        if ((threadIdx.x & 31) == 0) {
            atomicAdd(&g_acc[7 + s], a);
            atomicAdd(&g_acc[14 + s], b);
        }
    }
}

__global__ void final_kernel(float* out, int n) {
    if (blockIdx.x == 0 && threadIdx.x == 0) {
        double Hm[7], Ho[7];
        const double Ds[7] = {1024., 1024., 1024., 2048., 2048., 2048., 3072.};
        for (int i = 0; i < 7; i++) Hm[i] = g_acc[i] / 4096.0;
        for (int s = 0; s < 7; s++)
            Ho[s] = g_acc[7 + s] / 4096.0 - g_acc[14 + s] / (4096.0 * Ds[s]);
        double H1 = Hm[0] - Ho[0], H2 = Hm[1] - Ho[1], H3 = Hm[2] - Ho[2];
        double MI13 = (Ho[0] + Ho[2] - Ho[3]) - (Hm[0] + Hm[2] - Hm[3]);
        double MI23 = (Ho[1] + Ho[2] - Ho[4]) - (Hm[1] + Hm[2] - Hm[4]);
        double MI12 = (Ho[0] + Ho[1] - Ho[5]) - (Hm[0] + Hm[1] - Hm[5]);
        double data_mu = g_acc[3] + g_acc[4] - g_acc[2] - g_acc[6];
        double label_cmi = Ho[4] - Ho[2] + Ho[3] - Ho[6];
        double CMI = label_cmi - data_mu;
        double mse = 0.5 * g_acc[21] / (4096.0 * 3072.0);
        double loss = 0.9 * mse + 0.1 * (H1 * H1 + H2 * H2 + H3 * H3 + MI13 * MI13 +
                                         MI23 * MI23 + MI12 * MI12 + CMI * CMI);
        float lf = (float)loss;
        for (int i = 0; i < n; i++) out[i] = lf;
    }
}

extern "C" void kernel_launch(void* const* d_in, const int* in_sizes, int n_in,
                              void* d_out, int out_size) {
    const float* data = (const float*)d_in[0];
    const float* d1 = (const float*)d_in[1];
    const float* d2 = (const float*)d_in[2];
    const float* d3 = (const float*)d_in[3];
    const float* o1 = (const float*)d_in[4];
    const float* o2 = (const float*)d_in[5];
    const float* o3 = (const float*)d_in[6];
    const float* outp = (const float*)d_in[7];

    init_kernel<<<1, 32>>>();
    dim3 mg(512, 3);
    min_kernel<<<mg, 256>>>(d1, d2, d3);
    mse_kernel<<<1024, 256>>>(data, outp);
    row_kernel<<<NB, 256>>>(d1, d2, d3, o1, o2, o3);
    combine_kernel<<<NB / 256, 256>>>();
    final_kernel<<<1, 32>>>((float*)d_out, out_size);
}